// round 2
// baseline (speedup 1.0000x reference)
#include <cuda_runtime.h>
#include <math.h>

// Problem dims (fixed for this instance)
#define BB 64
#define LZ 128
#define EE 512
#define HH 512
#define VV 32000
#define TT 64

// ---------------- device scratch (static: no allocations allowed) ----------
__device__ float g_hT[2][HH * BB];       // hidden state, k-major: [k][b], double buffered
__device__ float g_xT[EE * BB];          // input x, k-major: [k][b]
__device__ float g_WfcT[EE * VV];        // W_fc transposed: [k][v]  (65.5 MB)

// ---------------- f32x2 helpers --------------------------------------------
__device__ __forceinline__ void fma2(unsigned long long& d, unsigned long long a,
                                     unsigned long long b) {
    asm("fma.rn.f32x2 %0, %1, %2, %0;" : "+l"(d) : "l"(a), "l"(b));
}
__device__ __forceinline__ unsigned long long dup2(float a) {
    unsigned long long r;
    asm("mov.b64 %0, {%1, %2};" : "=l"(r) : "f"(a), "f"(a));
    return r;
}

// ---------------- init: h0 = z @ W_proj^T + b_proj -------------------------
// block (64 b, 4 j), grid 128 -> j in [0,512)
__global__ void init_h_kernel(const float* __restrict__ z,
                              const float* __restrict__ Wp,
                              const float* __restrict__ bp) {
    int b = threadIdx.x;
    int j = blockIdx.x * 4 + threadIdx.y;
    float acc = 0.f;
    const float* zr = z + b * LZ;
    const float* wr = Wp + j * LZ;
#pragma unroll 4
    for (int l = 0; l < LZ; l++) acc += zr[l] * wr[l];
    acc += bp[j];
    g_hT[0][j * BB + b] = acc;
    g_xT[j * BB + b]    = acc;   // first step input x = h0
}

// ---------------- transpose W_fc [V][K] -> g_WfcT [K][V] -------------------
// block (32, 8), grid (V/32=1000, K/32=16)
__global__ void transpose_wfc_kernel(const float* __restrict__ Wfc) {
    __shared__ float tile[32][33];
    int v0 = blockIdx.x * 32;
    int k0 = blockIdx.y * 32;
    int tx = threadIdx.x, ty = threadIdx.y;
#pragma unroll
    for (int i = ty; i < 32; i += 8)
        tile[i][tx] = Wfc[(size_t)(v0 + i) * EE + (k0 + tx)];
    __syncthreads();
#pragma unroll
    for (int i = ty; i < 32; i += 8)
        g_WfcT[(size_t)(k0 + i) * VV + (v0 + tx)] = tile[tx][i];
}

// ---------------- GRU cell --------------------------------------------------
// thread = (b-pair lane, j). block (32, 8), grid 64 -> j in [0,512)
// Reads g_xT, g_hT[cur]; writes g_hT[1-cur].
__global__ void __launch_bounds__(256) gru_kernel(const float* __restrict__ Wih,
                                                  const float* __restrict__ bih,
                                                  const float* __restrict__ Whh,
                                                  const float* __restrict__ bhh,
                                                  int cur) {
    int bp = threadIdx.x;                       // 0..31 (pair of batches 2bp, 2bp+1)
    int j  = blockIdx.x * 8 + threadIdx.y;      // 0..511

    const float4* wri = (const float4*)(Wih + (size_t)j * EE);
    const float4* wzi = (const float4*)(Wih + (size_t)(j + HH) * EE);
    const float4* wni = (const float4*)(Wih + (size_t)(j + 2 * HH) * EE);
    const float4* wrh = (const float4*)(Whh + (size_t)j * HH);
    const float4* wzh = (const float4*)(Whh + (size_t)(j + HH) * HH);
    const float4* wnh = (const float4*)(Whh + (size_t)(j + 2 * HH) * HH);

    const float* xcol = g_xT + 2 * bp;
    const float* hcol = g_hT[cur] + 2 * bp;

    float air0 = 0.f, air1 = 0.f, aiz0 = 0.f, aiz1 = 0.f, ain0 = 0.f, ain1 = 0.f;
    float ahr0 = 0.f, ahr1 = 0.f, ahz0 = 0.f, ahz1 = 0.f, ahn0 = 0.f, ahn1 = 0.f;

#pragma unroll 2
    for (int k4 = 0; k4 < EE / 4; k4++) {
        float4 wa = wri[k4], wb = wzi[k4], wc = wni[k4];
        float4 wd = wrh[k4], we = wzh[k4], wf = wnh[k4];
#pragma unroll
        for (int s = 0; s < 4; s++) {
            int k = k4 * 4 + s;
            float2 x2 = *(const float2*)(xcol + (size_t)k * BB);
            float2 h2 = *(const float2*)(hcol + (size_t)k * BB);
            float wA = ((const float*)&wa)[s];
            float wB = ((const float*)&wb)[s];
            float wC = ((const float*)&wc)[s];
            float wD = ((const float*)&wd)[s];
            float wE = ((const float*)&we)[s];
            float wF = ((const float*)&wf)[s];
            air0 += wA * x2.x; air1 += wA * x2.y;
            aiz0 += wB * x2.x; aiz1 += wB * x2.y;
            ain0 += wC * x2.x; ain1 += wC * x2.y;
            ahr0 += wD * h2.x; ahr1 += wD * h2.y;
            ahz0 += wE * h2.x; ahz1 += wE * h2.y;
            ahn0 += wF * h2.x; ahn1 += wF * h2.y;
        }
    }

    float bir = bih[j], biz = bih[j + HH], bin = bih[j + 2 * HH];
    float bhr = bhh[j], bhz = bhh[j + HH], bhn = bhh[j + 2 * HH];

    float2 hprev = *(const float2*)(g_hT[cur] + (size_t)j * BB + 2 * bp);
    float* hout = g_hT[1 - cur] + (size_t)j * BB + 2 * bp;

    // batch 2bp
    {
        float r  = 1.f / (1.f + expf(-((air0 + bir) + (ahr0 + bhr))));
        float zg = 1.f / (1.f + expf(-((aiz0 + biz) + (ahz0 + bhz))));
        float n  = tanhf((ain0 + bin) + r * (ahn0 + bhn));
        hout[0]  = (1.f - zg) * n + zg * hprev.x;
    }
    // batch 2bp+1
    {
        float r  = 1.f / (1.f + expf(-((air1 + bir) + (ahr1 + bhr))));
        float zg = 1.f / (1.f + expf(-((aiz1 + biz) + (ahz1 + bhz))));
        float n  = tanhf((ain1 + bin) + r * (ahn1 + bhn));
        hout[1]  = (1.f - zg) * n + zg * hprev.y;
    }
}

// ---------------- logits: out[b][t][v] = h_new[b] . W_fc[v] + b_fc[v] ------
// 1 thread per v, all 64 batches in 32 f32x2 accumulators.
// grid 250, block 128 -> 32000 v.
__global__ void __launch_bounds__(128) logits_kernel(const float* __restrict__ bfc,
                                                     float* __restrict__ out,
                                                     int t, int hbuf) {
    __shared__ __align__(16) float sh[64 * 64];   // 16 KB chunk of h: [kk][b]
    int v = blockIdx.x * 128 + threadIdx.x;

    unsigned long long acc[32];
#pragma unroll
    for (int i = 0; i < 32; i++) acc[i] = 0ull;

    const float* hbase = g_hT[hbuf];

    for (int kc = 0; kc < EE; kc += 64) {
        __syncthreads();
        {
            const float4* src = (const float4*)(hbase + (size_t)kc * BB);
            float4* dst = (float4*)sh;
#pragma unroll
            for (int i = 0; i < 8; i++)
                dst[threadIdx.x + i * 128] = src[threadIdx.x + i * 128];
        }
        __syncthreads();

#pragma unroll 1
        for (int kk = 0; kk < 64; kk += 4) {
            float w0 = g_WfcT[(size_t)(kc + kk + 0) * VV + v];
            float w1 = g_WfcT[(size_t)(kc + kk + 1) * VV + v];
            float w2 = g_WfcT[(size_t)(kc + kk + 2) * VV + v];
            float w3 = g_WfcT[(size_t)(kc + kk + 3) * VV + v];

            unsigned long long W;
            const ulonglong2* hp;

            W = dup2(w0); hp = (const ulonglong2*)(sh + (kk + 0) * 64);
#pragma unroll
            for (int i = 0; i < 16; i++) { ulonglong2 hh = hp[i]; fma2(acc[2*i], W, hh.x); fma2(acc[2*i+1], W, hh.y); }
            W = dup2(w1); hp = (const ulonglong2*)(sh + (kk + 1) * 64);
#pragma unroll
            for (int i = 0; i < 16; i++) { ulonglong2 hh = hp[i]; fma2(acc[2*i], W, hh.x); fma2(acc[2*i+1], W, hh.y); }
            W = dup2(w2); hp = (const ulonglong2*)(sh + (kk + 2) * 64);
#pragma unroll
            for (int i = 0; i < 16; i++) { ulonglong2 hh = hp[i]; fma2(acc[2*i], W, hh.x); fma2(acc[2*i+1], W, hh.y); }
            W = dup2(w3); hp = (const ulonglong2*)(sh + (kk + 3) * 64);
#pragma unroll
            for (int i = 0; i < 16; i++) { ulonglong2 hh = hp[i]; fma2(acc[2*i], W, hh.x); fma2(acc[2*i+1], W, hh.y); }
        }
    }

    float bias = bfc[v];
    size_t ov = (size_t)t * VV + v;
#pragma unroll
    for (int i = 0; i < 32; i++) {
        float2 a = *(float2*)&acc[i];
        out[(size_t)(2 * i)     * TT * VV + ov] = a.x + bias;
        out[(size_t)(2 * i + 1) * TT * VV + ov] = a.y + bias;
    }
}

// ---------------- argmax over V + embedding gather into g_xT ---------------
// grid 64 (one block per batch row), block 256
__global__ void argmax_embed_kernel(const float* __restrict__ out,
                                    const float* __restrict__ emb, int t) {
    int b = blockIdx.x;
    int tid = threadIdx.x;
    const float* row = out + ((size_t)b * TT + t) * VV;

    float best = -3.4e38f;
    int bidx = 0;
    for (int v = tid; v < VV; v += 256) {
        float val = row[v];
        if (val > best) { best = val; bidx = v; }   // ascending v: first-max kept
    }

    __shared__ float sv[256];
    __shared__ int   si[256];
    sv[tid] = best; si[tid] = bidx;
    __syncthreads();
#pragma unroll
    for (int s = 128; s > 0; s >>= 1) {
        if (tid < s) {
            float ov_ = sv[tid + s]; int oi = si[tid + s];
            if (ov_ > sv[tid] || (ov_ == sv[tid] && oi < si[tid])) { sv[tid] = ov_; si[tid] = oi; }
        }
        __syncthreads();
    }
    int id = si[0];

    const float* er = emb + (size_t)id * EE;
    for (int k = tid; k < EE; k += 256) g_xT[(size_t)k * BB + b] = er[k];
}

// ---------------- launch ----------------------------------------------------
extern "C" void kernel_launch(void* const* d_in, const int* in_sizes, int n_in,
                              void* d_out, int out_size) {
    const float* z     = (const float*)d_in[0];
    const float* emb   = (const float*)d_in[1];
    const float* Wproj = (const float*)d_in[2];
    const float* bproj = (const float*)d_in[3];
    const float* Wih   = (const float*)d_in[4];
    const float* bih   = (const float*)d_in[5];
    const float* Whh   = (const float*)d_in[6];
    const float* bhh   = (const float*)d_in[7];
    const float* Wfc   = (const float*)d_in[8];
    const float* bfc   = (const float*)d_in[9];
    float* out = (float*)d_out;

    init_h_kernel<<<128, dim3(64, 4)>>>(z, Wproj, bproj);
    transpose_wfc_kernel<<<dim3(VV / 32, EE / 32), dim3(32, 8)>>>(Wfc);

    int cur = 0;
    for (int t = 0; t < TT; t++) {
        gru_kernel<<<64, dim3(32, 8)>>>(Wih, bih, Whh, bhh, cur);
        logits_kernel<<<250, 128>>>(bfc, out, t, 1 - cur);
        argmax_embed_kernel<<<64, 256>>>(out, emb, t);
        cur = 1 - cur;
    }
}

// round 3
// speedup vs baseline: 1.9379x; 1.9379x over previous
#include <cuda_runtime.h>
#include <math.h>

#define BB 64
#define LZ 128
#define EE 512
#define HH 512
#define VV 32000
#define TT 64

typedef unsigned long long ull;

// ---------------- device scratch ----------------
__device__ float g_hT[2][HH * BB];        // hidden state, k-major [k][b], double buffered
__device__ float g_xT[EE * BB];           // input x, k-major [k][b]
__device__ float g_WfcT[(size_t)EE * VV]; // W_fc transposed [k][v]
__device__ float2 g_pmax[250][BB];        // per-block partial argmax (val, idx-as-float)

// ---------------- f32x2 helpers ----------------
__device__ __forceinline__ void fma2(ull& d, ull a, ull b) {
    asm("fma.rn.f32x2 %0, %1, %2, %0;" : "+l"(d) : "l"(a), "l"(b));
}
__device__ __forceinline__ ull dup2(float a) {
    ull r;
    asm("mov.b64 %0, {%1, %2};" : "=l"(r) : "f"(a), "f"(a));
    return r;
}

// ---------------- init: h0 = z @ W_proj^T + b_proj ----------------
__global__ void init_h_kernel(const float* __restrict__ z,
                              const float* __restrict__ Wp,
                              const float* __restrict__ bp) {
    int b = threadIdx.x;
    int j = blockIdx.x * 4 + threadIdx.y;
    float acc = 0.f;
    const float* zr = z + b * LZ;
    const float* wr = Wp + j * LZ;
#pragma unroll 4
    for (int l = 0; l < LZ; l++) acc += zr[l] * wr[l];
    acc += bp[j];
    g_hT[0][j * BB + b] = acc;
    g_xT[j * BB + b]    = acc;
}

// ---------------- transpose W_fc [V][K] -> g_WfcT [K][V] ----------------
__global__ void transpose_wfc_kernel(const float* __restrict__ Wfc) {
    __shared__ float tile[32][33];
    int v0 = blockIdx.x * 32;
    int k0 = blockIdx.y * 32;
    int tx = threadIdx.x, ty = threadIdx.y;
#pragma unroll
    for (int i = ty; i < 32; i += 8)
        tile[i][tx] = Wfc[(size_t)(v0 + i) * EE + (k0 + tx)];
    __syncthreads();
#pragma unroll
    for (int i = ty; i < 32; i += 8)
        g_WfcT[(size_t)(k0 + i) * VV + (v0 + tx)] = tile[tx][i];
}

// ---------------- GRU cell ----------------
// block (32 bp, 2 j), grid 256 -> j in [0,512). Full-SM coverage.
__global__ void __launch_bounds__(64) gru_kernel(const float* __restrict__ Wih,
                                                 const float* __restrict__ bih,
                                                 const float* __restrict__ Whh,
                                                 const float* __restrict__ bhh,
                                                 int cur) {
    int bp = threadIdx.x;
    int j  = blockIdx.x * 2 + threadIdx.y;

    const float4* wri = (const float4*)(Wih + (size_t)j * EE);
    const float4* wzi = (const float4*)(Wih + (size_t)(j + HH) * EE);
    const float4* wni = (const float4*)(Wih + (size_t)(j + 2 * HH) * EE);
    const float4* wrh = (const float4*)(Whh + (size_t)j * HH);
    const float4* wzh = (const float4*)(Whh + (size_t)(j + HH) * HH);
    const float4* wnh = (const float4*)(Whh + (size_t)(j + 2 * HH) * HH);

    const float* xcol = g_xT + 2 * bp;
    const float* hcol = g_hT[cur] + 2 * bp;

    float air0 = 0.f, air1 = 0.f, aiz0 = 0.f, aiz1 = 0.f, ain0 = 0.f, ain1 = 0.f;
    float ahr0 = 0.f, ahr1 = 0.f, ahz0 = 0.f, ahz1 = 0.f, ahn0 = 0.f, ahn1 = 0.f;

#pragma unroll 2
    for (int k4 = 0; k4 < EE / 4; k4++) {
        float4 wa = wri[k4], wb = wzi[k4], wc = wni[k4];
        float4 wd = wrh[k4], we = wzh[k4], wf = wnh[k4];
#pragma unroll
        for (int s = 0; s < 4; s++) {
            int k = k4 * 4 + s;
            float2 x2 = *(const float2*)(xcol + (size_t)k * BB);
            float2 h2 = *(const float2*)(hcol + (size_t)k * BB);
            float wA = ((const float*)&wa)[s];
            float wB = ((const float*)&wb)[s];
            float wC = ((const float*)&wc)[s];
            float wD = ((const float*)&wd)[s];
            float wE = ((const float*)&we)[s];
            float wF = ((const float*)&wf)[s];
            air0 += wA * x2.x; air1 += wA * x2.y;
            aiz0 += wB * x2.x; aiz1 += wB * x2.y;
            ain0 += wC * x2.x; ain1 += wC * x2.y;
            ahr0 += wD * h2.x; ahr1 += wD * h2.y;
            ahz0 += wE * h2.x; ahz1 += wE * h2.y;
            ahn0 += wF * h2.x; ahn1 += wF * h2.y;
        }
    }

    float bir = bih[j], biz = bih[j + HH], bin = bih[j + 2 * HH];
    float bhr = bhh[j], bhz = bhh[j + HH], bhn = bhh[j + 2 * HH];

    float2 hprev = *(const float2*)(g_hT[cur] + (size_t)j * BB + 2 * bp);
    float* hout = g_hT[1 - cur] + (size_t)j * BB + 2 * bp;

    {
        float r  = 1.f / (1.f + expf(-((air0 + bir) + (ahr0 + bhr))));
        float zg = 1.f / (1.f + expf(-((aiz0 + biz) + (ahz0 + bhz))));
        float n  = tanhf((ain0 + bin) + r * (ahn0 + bhn));
        hout[0]  = (1.f - zg) * n + zg * hprev.x;
    }
    {
        float r  = 1.f / (1.f + expf(-((air1 + bir) + (ahr1 + bhr))));
        float zg = 1.f / (1.f + expf(-((aiz1 + biz) + (ahz1 + bhz))));
        float n  = tanhf((ain1 + bin) + r * (ahn1 + bhn));
        hout[1]  = (1.f - zg) * n + zg * hprev.y;
    }
}

// ---------------- logits + fused partial argmax ----------------
// grid 250 (128 v per block), block 128 = 16 vg x 8 bg.
// thread tile: 8 v (vA..vA+3, vB..vB+3) x 8 batches (bg*8..+8).
__global__ void __launch_bounds__(128, 2) logits_kernel(const float* __restrict__ bfc,
                                                        float* __restrict__ out,
                                                        int t, int hbuf) {
    __shared__ __align__(16) float sh[64 * 64];   // h chunk [kk][b]
    int tid = threadIdx.x;
    int vg = tid & 15;
    int bg = tid >> 4;
    int v0 = blockIdx.x * 128;
    int vA = v0 + vg * 4;
    int vB = vA + 64;

    ull acc[8][4];
#pragma unroll
    for (int v = 0; v < 8; v++)
#pragma unroll
        for (int p = 0; p < 4; p++) acc[v][p] = 0ull;

    const float* hbase = g_hT[hbuf];

    for (int kc = 0; kc < EE; kc += 64) {
        __syncthreads();
        {
            const float4* src = (const float4*)(hbase + (size_t)kc * BB);
            float4* dst = (float4*)sh;
#pragma unroll
            for (int i = 0; i < 8; i++)
                dst[tid + i * 128] = src[tid + i * 128];
        }
        __syncthreads();

#pragma unroll 4
        for (int kk = 0; kk < 64; kk++) {
            size_t krow = (size_t)(kc + kk) * VV;
            float4 wA = *(const float4*)&g_WfcT[krow + vA];
            float4 wB = *(const float4*)&g_WfcT[krow + vB];
            ulonglong2 h01 = *(const ulonglong2*)(sh + kk * 64 + bg * 8);
            ulonglong2 h23 = *(const ulonglong2*)(sh + kk * 64 + bg * 8 + 4);
            ull hb0 = h01.x, hb1 = h01.y, hb2 = h23.x, hb3 = h23.y;

#pragma unroll
            for (int v = 0; v < 4; v++) {
                ull W = dup2(((const float*)&wA)[v]);
                fma2(acc[v][0], W, hb0);
                fma2(acc[v][1], W, hb1);
                fma2(acc[v][2], W, hb2);
                fma2(acc[v][3], W, hb3);
            }
#pragma unroll
            for (int v = 0; v < 4; v++) {
                ull W = dup2(((const float*)&wB)[v]);
                fma2(acc[4 + v][0], W, hb0);
                fma2(acc[4 + v][1], W, hb1);
                fma2(acc[4 + v][2], W, hb2);
                fma2(acc[4 + v][3], W, hb3);
            }
        }
    }

    float4 biasA = *(const float4*)&bfc[vA];
    float4 biasB = *(const float4*)&bfc[vB];

#pragma unroll
    for (int i = 0; i < 8; i++) {
        int b = bg * 8 + i;
        int p = i >> 1, c = i & 1;

        float4 oA, oB;
        oA.x = ((const float*)&acc[0][p])[c] + biasA.x;
        oA.y = ((const float*)&acc[1][p])[c] + biasA.y;
        oA.z = ((const float*)&acc[2][p])[c] + biasA.z;
        oA.w = ((const float*)&acc[3][p])[c] + biasA.w;
        oB.x = ((const float*)&acc[4][p])[c] + biasB.x;
        oB.y = ((const float*)&acc[5][p])[c] + biasB.y;
        oB.z = ((const float*)&acc[6][p])[c] + biasB.z;
        oB.w = ((const float*)&acc[7][p])[c] + biasB.w;

        size_t rowoff = ((size_t)b * TT + t) * VV;
        __stcs((float4*)(out + rowoff + vA), oA);
        __stcs((float4*)(out + rowoff + vB), oB);

        // local argmax over this thread's 8 v (ascending v, strict > keeps first-max)
        float best = oA.x; int bidx = vA;
        if (oA.y > best) { best = oA.y; bidx = vA + 1; }
        if (oA.z > best) { best = oA.z; bidx = vA + 2; }
        if (oA.w > best) { best = oA.w; bidx = vA + 3; }
        if (oB.x > best) { best = oB.x; bidx = vB; }
        if (oB.y > best) { best = oB.y; bidx = vB + 1; }
        if (oB.z > best) { best = oB.z; bidx = vB + 2; }
        if (oB.w > best) { best = oB.w; bidx = vB + 3; }

        // reduce across the 16 vg lanes sharing this bg (lanes 0-15 / 16-31 in warp)
#pragma unroll
        for (int m = 1; m < 16; m <<= 1) {
            float ov = __shfl_xor_sync(0xffffffffu, best, m);
            int   oi = __shfl_xor_sync(0xffffffffu, bidx, m);
            if (ov > best || (ov == best && oi < bidx)) { best = ov; bidx = oi; }
        }
        if (vg == 0)
            g_pmax[blockIdx.x][b] = make_float2(best, __int_as_float(bidx));
    }
}

// ---------------- final argmax + embedding gather ----------------
// grid 64 (one block per batch), block 128
__global__ void argmax_embed_kernel(const float* __restrict__ emb) {
    int b = blockIdx.x;
    int tid = threadIdx.x;

    float best = -3.4e38f;
    int bidx = 0x7fffffff;
    for (int i = tid; i < 250; i += 128) {
        float2 p = g_pmax[i][b];
        float v = p.x;
        int idx = __float_as_int(p.y);
        if (v > best || (v == best && idx < bidx)) { best = v; bidx = idx; }
    }

    __shared__ float sv[128];
    __shared__ int   si[128];
    sv[tid] = best; si[tid] = bidx;
    __syncthreads();
#pragma unroll
    for (int s = 64; s > 0; s >>= 1) {
        if (tid < s) {
            float ov = sv[tid + s]; int oi = si[tid + s];
            if (ov > sv[tid] || (ov == sv[tid] && oi < si[tid])) { sv[tid] = ov; si[tid] = oi; }
        }
        __syncthreads();
    }
    int id = si[0];

    const float* er = emb + (size_t)id * EE;
    for (int k = tid; k < EE; k += 128) g_xT[(size_t)k * BB + b] = er[k];
}

// ---------------- launch ----------------
extern "C" void kernel_launch(void* const* d_in, const int* in_sizes, int n_in,
                              void* d_out, int out_size) {
    const float* z     = (const float*)d_in[0];
    const float* emb   = (const float*)d_in[1];
    const float* Wproj = (const float*)d_in[2];
    const float* bproj = (const float*)d_in[3];
    const float* Wih   = (const float*)d_in[4];
    const float* bih   = (const float*)d_in[5];
    const float* Whh   = (const float*)d_in[6];
    const float* bhh   = (const float*)d_in[7];
    const float* Wfc   = (const float*)d_in[8];
    const float* bfc   = (const float*)d_in[9];
    float* out = (float*)d_out;

    init_h_kernel<<<128, dim3(64, 4)>>>(z, Wproj, bproj);
    transpose_wfc_kernel<<<dim3(VV / 32, EE / 32), dim3(32, 8)>>>(Wfc);

    int cur = 0;
    for (int t = 0; t < TT; t++) {
        gru_kernel<<<256, dim3(32, 2)>>>(Wih, bih, Whh, bhh, cur);
        logits_kernel<<<250, 128>>>(bfc, out, t, 1 - cur);
        argmax_embed_kernel<<<64, 128>>>(emb);
        cur = 1 - cur;
    }
}

// round 4
// speedup vs baseline: 3.4055x; 1.7573x over previous
#include <cuda_runtime.h>
#include <math.h>

#define BB 64
#define LZ 128
#define EE 512
#define HH 512
#define VV 32000
#define TT 64
#define NVBLK 500   // logits blocks (64 v each)

typedef unsigned long long ull;

// ---------------- device scratch ----------------
__device__ float g_hT[2][HH * BB];        // hidden state, k-major [k][b], double buffered
__device__ float g_xT[EE * BB];           // input x, k-major [k][b]
__device__ float g_WfcT[(size_t)EE * VV]; // W_fc transposed [k][v]
__device__ float2 g_pmax[BB][NVBLK];      // per-(batch, block) partial argmax

// ---------------- f32x2 helpers ----------------
__device__ __forceinline__ void fma2(ull& d, ull a, ull b) {
    asm("fma.rn.f32x2 %0, %1, %2, %0;" : "+l"(d) : "l"(a), "l"(b));
}
__device__ __forceinline__ ull dup2(float a) {
    ull r;
    asm("mov.b64 %0, {%1, %2};" : "=l"(r) : "f"(a), "f"(a));
    return r;
}

// ---------------- init: h0 = z @ W_proj^T + b_proj ----------------
__global__ void init_h_kernel(const float* __restrict__ z,
                              const float* __restrict__ Wp,
                              const float* __restrict__ bp) {
    int b = threadIdx.x;
    int j = blockIdx.x * 4 + threadIdx.y;
    float acc = 0.f;
    const float* zr = z + b * LZ;
    const float* wr = Wp + j * LZ;
#pragma unroll 4
    for (int l = 0; l < LZ; l++) acc += zr[l] * wr[l];
    acc += bp[j];
    g_hT[0][j * BB + b] = acc;
    g_xT[j * BB + b]    = acc;
}

// ---------------- transpose W_fc [V][K] -> g_WfcT [K][V] ----------------
__global__ void transpose_wfc_kernel(const float* __restrict__ Wfc) {
    __shared__ float tile[32][33];
    int v0 = blockIdx.x * 32;
    int k0 = blockIdx.y * 32;
    int tx = threadIdx.x, ty = threadIdx.y;
#pragma unroll
    for (int i = ty; i < 32; i += 8)
        tile[i][tx] = Wfc[(size_t)(v0 + i) * EE + (k0 + tx)];
    __syncthreads();
#pragma unroll
    for (int i = ty; i < 32; i += 8)
        g_WfcT[(size_t)(k0 + i) * VV + (v0 + tx)] = tile[tx][i];
}

// ---------------- GRU cell, 4-way k-split ----------------
// block (32 bp, 2 j, 4 ks) = 256 threads, grid 256 -> j in [0,512)
__global__ void __launch_bounds__(256) gru_kernel(const float* __restrict__ Wih,
                                                  const float* __restrict__ bih,
                                                  const float* __restrict__ Whh,
                                                  const float* __restrict__ bhh,
                                                  int cur) {
    int bp = threadIdx.x;                     // 0..31
    int jy = threadIdx.y;                     // 0..1
    int ks = threadIdx.z;                     // 0..3 (k slice of 128)
    int j  = blockIdx.x * 2 + jy;

    const float4* wri = (const float4*)(Wih + (size_t)j * EE) + ks * 32;
    const float4* wzi = (const float4*)(Wih + (size_t)(j + HH) * EE) + ks * 32;
    const float4* wni = (const float4*)(Wih + (size_t)(j + 2 * HH) * EE) + ks * 32;
    const float4* wrh = (const float4*)(Whh + (size_t)j * HH) + ks * 32;
    const float4* wzh = (const float4*)(Whh + (size_t)(j + HH) * HH) + ks * 32;
    const float4* wnh = (const float4*)(Whh + (size_t)(j + 2 * HH) * HH) + ks * 32;

    const float* xcol = g_xT + 2 * bp + (size_t)(ks * 128) * BB;
    const float* hcol = g_hT[cur] + 2 * bp + (size_t)(ks * 128) * BB;

    float air0 = 0.f, air1 = 0.f, aiz0 = 0.f, aiz1 = 0.f, ain0 = 0.f, ain1 = 0.f;
    float ahr0 = 0.f, ahr1 = 0.f, ahz0 = 0.f, ahz1 = 0.f, ahn0 = 0.f, ahn1 = 0.f;

#pragma unroll 2
    for (int k4 = 0; k4 < 32; k4++) {
        float4 wa = wri[k4], wb = wzi[k4], wc = wni[k4];
        float4 wd = wrh[k4], we = wzh[k4], wf = wnh[k4];
#pragma unroll
        for (int s = 0; s < 4; s++) {
            int k = k4 * 4 + s;
            float2 x2 = *(const float2*)(xcol + (size_t)k * BB);
            float2 h2 = *(const float2*)(hcol + (size_t)k * BB);
            float wA = ((const float*)&wa)[s];
            float wB = ((const float*)&wb)[s];
            float wC = ((const float*)&wc)[s];
            float wD = ((const float*)&wd)[s];
            float wE = ((const float*)&we)[s];
            float wF = ((const float*)&wf)[s];
            air0 += wA * x2.x; air1 += wA * x2.y;
            aiz0 += wB * x2.x; aiz1 += wB * x2.y;
            ain0 += wC * x2.x; ain1 += wC * x2.y;
            ahr0 += wD * h2.x; ahr1 += wD * h2.y;
            ahz0 += wE * h2.x; ahz1 += wE * h2.y;
            ahn0 += wF * h2.x; ahn1 += wF * h2.y;
        }
    }

    // reduce 4 k-slices through shared memory
    __shared__ float2 sred[4][2][6][32];
    sred[ks][jy][0][bp] = make_float2(air0, air1);
    sred[ks][jy][1][bp] = make_float2(aiz0, aiz1);
    sred[ks][jy][2][bp] = make_float2(ain0, ain1);
    sred[ks][jy][3][bp] = make_float2(ahr0, ahr1);
    sred[ks][jy][4][bp] = make_float2(ahz0, ahz1);
    sred[ks][jy][5][bp] = make_float2(ahn0, ahn1);
    __syncthreads();

    if (ks == 0) {
        float g[6][2];
#pragma unroll
        for (int gi = 0; gi < 6; gi++) {
            float2 s0 = sred[0][jy][gi][bp];
            float2 s1 = sred[1][jy][gi][bp];
            float2 s2 = sred[2][jy][gi][bp];
            float2 s3 = sred[3][jy][gi][bp];
            g[gi][0] = (s0.x + s1.x) + (s2.x + s3.x);
            g[gi][1] = (s0.y + s1.y) + (s2.y + s3.y);
        }

        float bir = bih[j], biz = bih[j + HH], bin = bih[j + 2 * HH];
        float bhr = bhh[j], bhz = bhh[j + HH], bhn = bhh[j + 2 * HH];

        float2 hprev = *(const float2*)(g_hT[cur] + (size_t)j * BB + 2 * bp);
        float* hout = g_hT[1 - cur] + (size_t)j * BB + 2 * bp;

        {
            float r  = 1.f / (1.f + expf(-((g[0][0] + bir) + (g[3][0] + bhr))));
            float zg = 1.f / (1.f + expf(-((g[1][0] + biz) + (g[4][0] + bhz))));
            float n  = tanhf((g[2][0] + bin) + r * (g[5][0] + bhn));
            hout[0]  = (1.f - zg) * n + zg * hprev.x;
        }
        {
            float r  = 1.f / (1.f + expf(-((g[0][1] + bir) + (g[3][1] + bhr))));
            float zg = 1.f / (1.f + expf(-((g[1][1] + biz) + (g[4][1] + bhz))));
            float n  = tanhf((g[2][1] + bin) + r * (g[5][1] + bhn));
            hout[1]  = (1.f - zg) * n + zg * hprev.y;
        }
    }
}

// ---------------- logits + fused partial argmax ----------------
// grid 500 (64 v per block), block 128 = 16 vg x 8 bg, tile 4v x 8b.
// All 500 blocks resident (4 blocks/SM) -> single wave, no tail.
__global__ void __launch_bounds__(128, 4) logits_kernel(const float* __restrict__ bfc,
                                                        float* __restrict__ out,
                                                        int t, int hbuf) {
    __shared__ __align__(16) float sh[64 * 64];   // h chunk [kk][b], 16 KB
    int tid = threadIdx.x;
    int vg = tid & 15;
    int bg = tid >> 4;
    int vA = blockIdx.x * 64 + vg * 4;

    ull acc[4][4];
#pragma unroll
    for (int v = 0; v < 4; v++)
#pragma unroll
        for (int p = 0; p < 4; p++) acc[v][p] = 0ull;

    const float* hbase = g_hT[hbuf];

    for (int kc = 0; kc < EE; kc += 64) {
        __syncthreads();
        {
            const float4* src = (const float4*)(hbase + (size_t)kc * BB);
            float4* dst = (float4*)sh;
#pragma unroll
            for (int i = 0; i < 8; i++)
                dst[tid + i * 128] = src[tid + i * 128];
        }
        __syncthreads();

#pragma unroll 4
        for (int kk = 0; kk < 64; kk++) {
            size_t krow = (size_t)(kc + kk) * VV;
            float4 w = *(const float4*)&g_WfcT[krow + vA];
            ulonglong2 h01 = *(const ulonglong2*)(sh + kk * 64 + bg * 8);
            ulonglong2 h23 = *(const ulonglong2*)(sh + kk * 64 + bg * 8 + 4);

            ull W0 = dup2(w.x), W1 = dup2(w.y), W2 = dup2(w.z), W3 = dup2(w.w);
            fma2(acc[0][0], W0, h01.x); fma2(acc[0][1], W0, h01.y);
            fma2(acc[0][2], W0, h23.x); fma2(acc[0][3], W0, h23.y);
            fma2(acc[1][0], W1, h01.x); fma2(acc[1][1], W1, h01.y);
            fma2(acc[1][2], W1, h23.x); fma2(acc[1][3], W1, h23.y);
            fma2(acc[2][0], W2, h01.x); fma2(acc[2][1], W2, h01.y);
            fma2(acc[2][2], W2, h23.x); fma2(acc[2][3], W2, h23.y);
            fma2(acc[3][0], W3, h01.x); fma2(acc[3][1], W3, h01.y);
            fma2(acc[3][2], W3, h23.x); fma2(acc[3][3], W3, h23.y);
        }
    }

    float4 bias = *(const float4*)&bfc[vA];

#pragma unroll
    for (int i = 0; i < 8; i++) {
        int b = bg * 8 + i;
        int p = i >> 1, c = i & 1;

        float4 o;
        o.x = ((const float*)&acc[0][p])[c] + bias.x;
        o.y = ((const float*)&acc[1][p])[c] + bias.y;
        o.z = ((const float*)&acc[2][p])[c] + bias.z;
        o.w = ((const float*)&acc[3][p])[c] + bias.w;

        size_t rowoff = ((size_t)b * TT + t) * VV;
        __stcs((float4*)(out + rowoff + vA), o);

        // local argmax over this thread's 4 v (ascending, strict > keeps first-max)
        float best = o.x; int bidx = vA;
        if (o.y > best) { best = o.y; bidx = vA + 1; }
        if (o.z > best) { best = o.z; bidx = vA + 2; }
        if (o.w > best) { best = o.w; bidx = vA + 3; }

        // reduce across the 16 vg lanes sharing this bg
#pragma unroll
        for (int m = 1; m < 16; m <<= 1) {
            float ov = __shfl_xor_sync(0xffffffffu, best, m);
            int   oi = __shfl_xor_sync(0xffffffffu, bidx, m);
            if (ov > best || (ov == best && oi < bidx)) { best = ov; bidx = oi; }
        }
        if (vg == 0)
            g_pmax[b][blockIdx.x] = make_float2(best, __int_as_float(bidx));
    }
}

// ---------------- final argmax + embedding gather ----------------
// grid 64 (one block per batch), block 128
__global__ void argmax_embed_kernel(const float* __restrict__ emb) {
    int b = blockIdx.x;
    int tid = threadIdx.x;

    float best = -3.4e38f;
    int bidx = 0x7fffffff;
    for (int i = tid; i < NVBLK; i += 128) {
        float2 p = g_pmax[b][i];
        float v = p.x;
        int idx = __float_as_int(p.y);
        if (v > best || (v == best && idx < bidx)) { best = v; bidx = idx; }
    }

    __shared__ float sv[128];
    __shared__ int   si[128];
    sv[tid] = best; si[tid] = bidx;
    __syncthreads();
#pragma unroll
    for (int s = 64; s > 0; s >>= 1) {
        if (tid < s) {
            float ov = sv[tid + s]; int oi = si[tid + s];
            if (ov > sv[tid] || (ov == sv[tid] && oi < si[tid])) { sv[tid] = ov; si[tid] = oi; }
        }
        __syncthreads();
    }
    int id = si[0];

    const float* er = emb + (size_t)id * EE;
    for (int k = tid; k < EE; k += 128) g_xT[(size_t)k * BB + b] = er[k];
}

// ---------------- launch ----------------
extern "C" void kernel_launch(void* const* d_in, const int* in_sizes, int n_in,
                              void* d_out, int out_size) {
    const float* z     = (const float*)d_in[0];
    const float* emb   = (const float*)d_in[1];
    const float* Wproj = (const float*)d_in[2];
    const float* bproj = (const float*)d_in[3];
    const float* Wih   = (const float*)d_in[4];
    const float* bih   = (const float*)d_in[5];
    const float* Whh   = (const float*)d_in[6];
    const float* bhh   = (const float*)d_in[7];
    const float* Wfc   = (const float*)d_in[8];
    const float* bfc   = (const float*)d_in[9];
    float* out = (float*)d_out;

    init_h_kernel<<<128, dim3(64, 4)>>>(z, Wproj, bproj);
    transpose_wfc_kernel<<<dim3(VV / 32, EE / 32), dim3(32, 8)>>>(Wfc);

    int cur = 0;
    for (int t = 0; t < TT; t++) {
        gru_kernel<<<256, dim3(32, 2, 4)>>>(Wih, bih, Whh, bhh, cur);
        logits_kernel<<<NVBLK, 128>>>(bfc, out, t, 1 - cur);
        argmax_embed_kernel<<<64, 128>>>(emb);
        cur = 1 - cur;
    }
}

// round 5
// speedup vs baseline: 4.1452x; 1.2172x over previous
#include <cuda_runtime.h>
#include <math.h>

#define BB 64
#define LZ 128
#define EE 512
#define HH 512
#define VV 32000
#define TT 64
#define NVBLK 500   // logits blocks (64 v each)
#define KCH 32      // k-chunk size in logits pipeline
#define NCHUNK (EE / KCH)  // 16

typedef unsigned long long ull;

// ---------------- device scratch ----------------
__device__ float g_hT[2][HH * BB];        // hidden state, k-major [k][b], double buffered
__device__ float g_xT[EE * BB];           // input x, k-major [k][b]
__device__ float g_WfcT[(size_t)EE * VV]; // W_fc transposed [k][v]
__device__ float2 g_pmax[BB][NVBLK];      // per-(batch, block) partial argmax

// ---------------- helpers ----------------
__device__ __forceinline__ void fma2(ull& d, ull a, ull b) {
    asm("fma.rn.f32x2 %0, %1, %2, %0;" : "+l"(d) : "l"(a), "l"(b));
}
__device__ __forceinline__ ull dup2(float a) {
    ull r;
    asm("mov.b64 %0, {%1, %2};" : "=l"(r) : "f"(a), "f"(a));
    return r;
}
__device__ __forceinline__ void cp_async16(void* smem, const void* gmem) {
    unsigned s = (unsigned)__cvta_generic_to_shared(smem);
    asm volatile("cp.async.cg.shared.global [%0], [%1], 16;\n" :: "r"(s), "l"(gmem));
}
__device__ __forceinline__ void cp_commit() {
    asm volatile("cp.async.commit_group;\n");
}

// ---------------- init: h0 = z @ W_proj^T + b_proj ----------------
__global__ void init_h_kernel(const float* __restrict__ z,
                              const float* __restrict__ Wp,
                              const float* __restrict__ bp) {
    int b = threadIdx.x;
    int j = blockIdx.x * 4 + threadIdx.y;
    float acc = 0.f;
    const float* zr = z + b * LZ;
    const float* wr = Wp + j * LZ;
#pragma unroll 4
    for (int l = 0; l < LZ; l++) acc += zr[l] * wr[l];
    acc += bp[j];
    g_hT[0][j * BB + b] = acc;
    g_xT[j * BB + b]    = acc;
}

// ---------------- transpose W_fc [V][K] -> g_WfcT [K][V] ----------------
__global__ void transpose_wfc_kernel(const float* __restrict__ Wfc) {
    __shared__ float tile[32][33];
    int v0 = blockIdx.x * 32;
    int k0 = blockIdx.y * 32;
    int tx = threadIdx.x, ty = threadIdx.y;
#pragma unroll
    for (int i = ty; i < 32; i += 8)
        tile[i][tx] = Wfc[(size_t)(v0 + i) * EE + (k0 + tx)];
    __syncthreads();
#pragma unroll
    for (int i = ty; i < 32; i += 8)
        g_WfcT[(size_t)(k0 + i) * VV + (v0 + tx)] = tile[tx][i];
}

// ---------------- GRU cell, 4-way k-split ----------------
// block (32 bp, 2 j, 4 ks) = 256 threads, grid 256 -> j in [0,512)
__global__ void __launch_bounds__(256) gru_kernel(const float* __restrict__ Wih,
                                                  const float* __restrict__ bih,
                                                  const float* __restrict__ Whh,
                                                  const float* __restrict__ bhh,
                                                  int cur) {
    int bp = threadIdx.x;
    int jy = threadIdx.y;
    int ks = threadIdx.z;
    int j  = blockIdx.x * 2 + jy;

    const float4* wri = (const float4*)(Wih + (size_t)j * EE) + ks * 32;
    const float4* wzi = (const float4*)(Wih + (size_t)(j + HH) * EE) + ks * 32;
    const float4* wni = (const float4*)(Wih + (size_t)(j + 2 * HH) * EE) + ks * 32;
    const float4* wrh = (const float4*)(Whh + (size_t)j * HH) + ks * 32;
    const float4* wzh = (const float4*)(Whh + (size_t)(j + HH) * HH) + ks * 32;
    const float4* wnh = (const float4*)(Whh + (size_t)(j + 2 * HH) * HH) + ks * 32;

    const float* xcol = g_xT + 2 * bp + (size_t)(ks * 128) * BB;
    const float* hcol = g_hT[cur] + 2 * bp + (size_t)(ks * 128) * BB;

    float air0 = 0.f, air1 = 0.f, aiz0 = 0.f, aiz1 = 0.f, ain0 = 0.f, ain1 = 0.f;
    float ahr0 = 0.f, ahr1 = 0.f, ahz0 = 0.f, ahz1 = 0.f, ahn0 = 0.f, ahn1 = 0.f;

#pragma unroll 2
    for (int k4 = 0; k4 < 32; k4++) {
        float4 wa = wri[k4], wb = wzi[k4], wc = wni[k4];
        float4 wd = wrh[k4], we = wzh[k4], wf = wnh[k4];
#pragma unroll
        for (int s = 0; s < 4; s++) {
            int k = k4 * 4 + s;
            float2 x2 = *(const float2*)(xcol + (size_t)k * BB);
            float2 h2 = *(const float2*)(hcol + (size_t)k * BB);
            float wA = ((const float*)&wa)[s];
            float wB = ((const float*)&wb)[s];
            float wC = ((const float*)&wc)[s];
            float wD = ((const float*)&wd)[s];
            float wE = ((const float*)&we)[s];
            float wF = ((const float*)&wf)[s];
            air0 += wA * x2.x; air1 += wA * x2.y;
            aiz0 += wB * x2.x; aiz1 += wB * x2.y;
            ain0 += wC * x2.x; ain1 += wC * x2.y;
            ahr0 += wD * h2.x; ahr1 += wD * h2.y;
            ahz0 += wE * h2.x; ahz1 += wE * h2.y;
            ahn0 += wF * h2.x; ahn1 += wF * h2.y;
        }
    }

    __shared__ float2 sred[4][2][6][32];
    sred[ks][jy][0][bp] = make_float2(air0, air1);
    sred[ks][jy][1][bp] = make_float2(aiz0, aiz1);
    sred[ks][jy][2][bp] = make_float2(ain0, ain1);
    sred[ks][jy][3][bp] = make_float2(ahr0, ahr1);
    sred[ks][jy][4][bp] = make_float2(ahz0, ahz1);
    sred[ks][jy][5][bp] = make_float2(ahn0, ahn1);
    __syncthreads();

    if (ks == 0) {
        float g[6][2];
#pragma unroll
        for (int gi = 0; gi < 6; gi++) {
            float2 s0 = sred[0][jy][gi][bp];
            float2 s1 = sred[1][jy][gi][bp];
            float2 s2 = sred[2][jy][gi][bp];
            float2 s3 = sred[3][jy][gi][bp];
            g[gi][0] = (s0.x + s1.x) + (s2.x + s3.x);
            g[gi][1] = (s0.y + s1.y) + (s2.y + s3.y);
        }

        float bir = bih[j], biz = bih[j + HH], bin = bih[j + 2 * HH];
        float bhr = bhh[j], bhz = bhh[j + HH], bhn = bhh[j + 2 * HH];

        float2 hprev = *(const float2*)(g_hT[cur] + (size_t)j * BB + 2 * bp);
        float* hout = g_hT[1 - cur] + (size_t)j * BB + 2 * bp;

        {
            float r  = 1.f / (1.f + expf(-((g[0][0] + bir) + (g[3][0] + bhr))));
            float zg = 1.f / (1.f + expf(-((g[1][0] + biz) + (g[4][0] + bhz))));
            float n  = tanhf((g[2][0] + bin) + r * (g[5][0] + bhn));
            hout[0]  = (1.f - zg) * n + zg * hprev.x;
        }
        {
            float r  = 1.f / (1.f + expf(-((g[0][1] + bir) + (g[3][1] + bhr))));
            float zg = 1.f / (1.f + expf(-((g[1][1] + biz) + (g[4][1] + bhz))));
            float n  = tanhf((g[2][1] + bin) + r * (g[5][1] + bhn));
            hout[1]  = (1.f - zg) * n + zg * hprev.y;
        }
    }
}

// ---------------- logits + fused partial argmax (cp.async pipelined) -------
// grid 500 (64 v per block), block 128 = 16 vg x 8 bg, tile 4v x 8b.
// 16 chunks of 32 kk; W and h chunks double-buffered in shared via cp.async.
__global__ void __launch_bounds__(128, 4) logits_kernel(const float* __restrict__ bfc,
                                                        float* __restrict__ out,
                                                        int t, int hbuf) {
    __shared__ __align__(16) float sW[2][KCH * 64];  // 8 KB each
    __shared__ __align__(16) float sH[2][KCH * 64];  // 8 KB each

    int tid = threadIdx.x;
    int vg = tid & 15;
    int bg = tid >> 4;
    int v0 = blockIdx.x * 64;
    int vA = v0 + vg * 4;

    const float* hbase = g_hT[hbuf];

    // issue cp.async for chunk c into buffer buf
    auto issue_chunk = [&](int c, int buf) {
        int kc = c * KCH;
#pragma unroll
        for (int p = 0; p < 4; p++) {
            int linear = tid + p * 128;          // 0..511
            int kk = linear >> 4;
            int sub = linear & 15;
            cp_async16(&sW[buf][kk * 64 + sub * 4],
                       &g_WfcT[(size_t)(kc + kk) * VV + v0 + sub * 4]);
        }
#pragma unroll
        for (int p = 0; p < 4; p++) {
            int linear = tid + p * 128;
            int kk = linear >> 4;
            int sub = linear & 15;
            cp_async16(&sH[buf][kk * 64 + sub * 4],
                       &hbase[(size_t)(kc + kk) * BB + sub * 4]);
        }
        cp_commit();
    };

    ull acc[4][4];
#pragma unroll
    for (int v = 0; v < 4; v++)
#pragma unroll
        for (int p = 0; p < 4; p++) acc[v][p] = 0ull;

    issue_chunk(0, 0);
    issue_chunk(1, 1);

#pragma unroll 1
    for (int c = 0; c < NCHUNK; c++) {
        if (c < NCHUNK - 1) asm volatile("cp.async.wait_group 1;\n");
        else                asm volatile("cp.async.wait_group 0;\n");
        __syncthreads();

        const float* Wb = sW[c & 1];
        const float* Hb = sH[c & 1];

#pragma unroll
        for (int kk = 0; kk < KCH; kk++) {
            float4 w = *(const float4*)(Wb + kk * 64 + vg * 4);
            ulonglong2 h01 = *(const ulonglong2*)(Hb + kk * 64 + bg * 8);
            ulonglong2 h23 = *(const ulonglong2*)(Hb + kk * 64 + bg * 8 + 4);

            ull W0 = dup2(w.x), W1 = dup2(w.y), W2 = dup2(w.z), W3 = dup2(w.w);
            fma2(acc[0][0], W0, h01.x); fma2(acc[0][1], W0, h01.y);
            fma2(acc[0][2], W0, h23.x); fma2(acc[0][3], W0, h23.y);
            fma2(acc[1][0], W1, h01.x); fma2(acc[1][1], W1, h01.y);
            fma2(acc[1][2], W1, h23.x); fma2(acc[1][3], W1, h23.y);
            fma2(acc[2][0], W2, h01.x); fma2(acc[2][1], W2, h01.y);
            fma2(acc[2][2], W2, h23.x); fma2(acc[2][3], W2, h23.y);
            fma2(acc[3][0], W3, h01.x); fma2(acc[3][1], W3, h01.y);
            fma2(acc[3][2], W3, h23.x); fma2(acc[3][3], W3, h23.y);
        }

        __syncthreads();                 // everyone done with buffer (c&1)
        if (c + 2 < NCHUNK) issue_chunk(c + 2, c & 1);
    }

    float4 bias = *(const float4*)&bfc[vA];

#pragma unroll
    for (int i = 0; i < 8; i++) {
        int b = bg * 8 + i;
        int p = i >> 1, cc = i & 1;

        float4 o;
        o.x = ((const float*)&acc[0][p])[cc] + bias.x;
        o.y = ((const float*)&acc[1][p])[cc] + bias.y;
        o.z = ((const float*)&acc[2][p])[cc] + bias.z;
        o.w = ((const float*)&acc[3][p])[cc] + bias.w;

        size_t rowoff = ((size_t)b * TT + t) * VV;
        __stcs((float4*)(out + rowoff + vA), o);

        float best = o.x; int bidx = vA;
        if (o.y > best) { best = o.y; bidx = vA + 1; }
        if (o.z > best) { best = o.z; bidx = vA + 2; }
        if (o.w > best) { best = o.w; bidx = vA + 3; }

#pragma unroll
        for (int m = 1; m < 16; m <<= 1) {
            float ov = __shfl_xor_sync(0xffffffffu, best, m);
            int   oi = __shfl_xor_sync(0xffffffffu, bidx, m);
            if (ov > best || (ov == best && oi < bidx)) { best = ov; bidx = oi; }
        }
        if (vg == 0)
            g_pmax[b][blockIdx.x] = make_float2(best, __int_as_float(bidx));
    }
}

// ---------------- final argmax + embedding gather ----------------
__global__ void argmax_embed_kernel(const float* __restrict__ emb) {
    int b = blockIdx.x;
    int tid = threadIdx.x;

    float best = -3.4e38f;
    int bidx = 0x7fffffff;
    for (int i = tid; i < NVBLK; i += 128) {
        float2 p = g_pmax[b][i];
        float v = p.x;
        int idx = __float_as_int(p.y);
        if (v > best || (v == best && idx < bidx)) { best = v; bidx = idx; }
    }

    __shared__ float sv[128];
    __shared__ int   si[128];
    sv[tid] = best; si[tid] = bidx;
    __syncthreads();
#pragma unroll
    for (int s = 64; s > 0; s >>= 1) {
        if (tid < s) {
            float ov = sv[tid + s]; int oi = si[tid + s];
            if (ov > sv[tid] || (ov == sv[tid] && oi < si[tid])) { sv[tid] = ov; si[tid] = oi; }
        }
        __syncthreads();
    }
    int id = si[0];

    const float* er = emb + (size_t)id * EE;
    for (int k = tid; k < EE; k += 128) g_xT[(size_t)k * BB + b] = er[k];
}

// ---------------- launch ----------------
extern "C" void kernel_launch(void* const* d_in, const int* in_sizes, int n_in,
                              void* d_out, int out_size) {
    const float* z     = (const float*)d_in[0];
    const float* emb   = (const float*)d_in[1];
    const float* Wproj = (const float*)d_in[2];
    const float* bproj = (const float*)d_in[3];
    const float* Wih   = (const float*)d_in[4];
    const float* bih   = (const float*)d_in[5];
    const float* Whh   = (const float*)d_in[6];
    const float* bhh   = (const float*)d_in[7];
    const float* Wfc   = (const float*)d_in[8];
    const float* bfc   = (const float*)d_in[9];
    float* out = (float*)d_out;

    init_h_kernel<<<128, dim3(64, 4)>>>(z, Wproj, bproj);
    transpose_wfc_kernel<<<dim3(VV / 32, EE / 32), dim3(32, 8)>>>(Wfc);

    int cur = 0;
    for (int t = 0; t < TT; t++) {
        gru_kernel<<<256, dim3(32, 2, 4)>>>(Wih, bih, Whh, bhh, cur);
        logits_kernel<<<NVBLK, 128>>>(bfc, out, t, 1 - cur);
        argmax_embed_kernel<<<64, 128>>>(emb);
        cur = 1 - cur;
    }
}